// round 8
// baseline (speedup 1.0000x reference)
#include <cuda_runtime.h>
#include <math_constants.h>

#define BB 2
#define NN 32768
#define MM 4096
#define M2 (MM / 2)
#define CC 128
#define OUTC 128
#define INC 131
#define HPAD 132

typedef unsigned long long ull;

// ---------------------------------------------------------------------------
// Scratch (__device__ globals). Weight arrays padded for prefetch overreads.
// ---------------------------------------------------------------------------
__device__ __align__(16) float g_w1q[34 * 128 * 4];  // [kq][o][4] permuted w1
__device__ __align__(16) float g_w2q[33 * 128 * 4];  // [kq][o][4] w2
__device__ int g_idx[BB * NN * 3];

// ---------------------------------------------------------------------------
// f32x2 helpers (FFMA2 is PTX-only)
// ---------------------------------------------------------------------------
__device__ __forceinline__ ull fma2(ull a, ull b, ull c) {
    ull d;
    asm("fma.rn.f32x2 %0, %1, %2, %3;" : "=l"(d) : "l"(a), "l"(b), "l"(c));
    return d;
}
__device__ __forceinline__ ull pack2(float a, float b) {
    ull r;
    asm("mov.b64 %0, {%1, %2};" : "=l"(r)
        : "r"(__float_as_uint(a)), "r"(__float_as_uint(b)));
    return r;
}
__device__ __forceinline__ float2 unpack2(ull v) {
    unsigned int lo, hi;
    asm("mov.b64 {%0, %1}, %2;" : "=r"(lo), "=r"(hi) : "l"(v));
    return make_float2(__uint_as_float(lo), __uint_as_float(hi));
}

// branchless strict-< top-3 merge (flat compare-select, no BSSY)
__device__ __forceinline__ void bmerge(float v, int j,
    float& m0, float& m1, float& m2, int& i0, int& i1, int& i2) {
    bool p0 = v < m0, p1 = v < m1, p2 = v < m2;
    float nm2 = p1 ? m1 : (p2 ? v : m2);
    int   ni2 = p1 ? i1 : (p2 ? j : i2);
    float nm1 = p0 ? m0 : (p1 ? v : m1);
    int   ni1 = p0 ? i0 : (p1 ? j : i1);
    float nm0 = p0 ? v : m0;
    int   ni0 = p0 ? j : i0;
    m0 = nm0; m1 = nm1; m2 = nm2;
    i0 = ni0; i1 = ni1; i2 = ni2;
}

// ---------------------------------------------------------------------------
// Kernel 0: weight prep
// ---------------------------------------------------------------------------
#define W1_W (33 * 128)
#define W2_W (32 * 128)
#define WPREP_ITEMS (W1_W + W2_W)           // 8320
#define WPREP_BLOCKS ((WPREP_ITEMS + 127) / 128)

__global__ void __launch_bounds__(128) wprep_kernel(
    const float* __restrict__ w1, const float* __restrict__ w2) {
    int i = blockIdx.x * 128 + threadIdx.x;
    if (i < W1_W) {
        int kq = i >> 7, o = i & 127;
        float v[4];
#pragma unroll
        for (int q = 0; q < 4; q++) {
            int k = kq * 4 + q;
            if (k < 128)      v[q] = w1[o * INC + 3 + k];
            else if (k < 131) v[q] = w1[o * INC + (k - 128)];
            else              v[q] = 0.f;
        }
        *(float4*)&g_w1q[i * 4] = make_float4(v[0], v[1], v[2], v[3]);
    } else if (i < WPREP_ITEMS) {
        int t = i - W1_W;
        int kq = t >> 7, o = t & 127;
        const float* wr = w2 + o * 128 + kq * 4;
        *(float4*)&g_w2q[t * 4] = make_float4(wr[0], wr[1], wr[2], wr[3]);
    }
}

// ---------------------------------------------------------------------------
// Kernel 1: kNN — 128 threads, 2 queries/thread, two-pass flag-and-replay
//   launched twice (block offset) so ncu can capture it
// ---------------------------------------------------------------------------
__global__ void __launch_bounds__(128) knn_kernel(
    const float* __restrict__ x, const float* __restrict__ sx, int blk0) {
    extern __shared__ float4 sm4[];
    float4* skA = sm4;        // (-2sx_j,-2sx_j1,-2sy_j,-2sy_j1)  32KB
    float4* skB = sm4 + M2;   // (-2sz_j,-2sz_j1,|s_j|^2,|s_j1|^2) 32KB

    const int q0  = (blk0 + blockIdx.x) * 256;
    const int b   = q0 / NN;
    const int tid = threadIdx.x;

    const float* sxb = sx + (size_t)b * MM * 3;
    for (int j2 = tid; j2 < M2; j2 += 128) {
        const float* p = sxb + (size_t)j2 * 6;
        float a0 = p[0], a1 = p[1], a2 = p[2];
        float c0 = p[3], c1 = p[4], c2 = p[5];
        skA[j2] = make_float4(-2.f * a0, -2.f * c0, -2.f * a1, -2.f * c1);
        skB[j2] = make_float4(-2.f * a2, -2.f * c2,
                              a0 * a0 + a1 * a1 + a2 * a2,
                              c0 * c0 + c1 * c1 + c2 * c2);
    }
    __syncthreads();

    const int qa = q0 + tid;
    const int qb = q0 + 128 + tid;
    float xa0 = x[qa * 3 + 0], xa1 = x[qa * 3 + 1], xa2 = x[qa * 3 + 2];
    float xb0 = x[qb * 3 + 0], xb1 = x[qb * 3 + 1], xb2 = x[qb * 3 + 2];
    const ull ax0 = pack2(xa0, xa0), ax1 = pack2(xa1, xa1), ax2 = pack2(xa2, xa2);
    const ull bx0 = pack2(xb0, xb0), bx1 = pack2(xb1, xb1), bx2 = pack2(xb2, xb2);

    const ulonglong2* A2 = (const ulonglong2*)skA;
    const ulonglong2* B2 = (const ulonglong2*)skB;

    // ---- pass 1: branchless chunk-min bound + flag bits (both queries) ----
    float am0 = CUDART_INF_F, am1 = CUDART_INF_F, am2 = CUDART_INF_F;
    float bm0 = CUDART_INF_F, bm1 = CUDART_INF_F, bm2 = CUDART_INF_F;
    unsigned fa[8], fb[8];

#pragma unroll
    for (int w8 = 0; w8 < 8; w8++) {
        unsigned fma_ = 0, fmb_ = 0;
#pragma unroll 1
        for (int cb = 0; cb < 32; cb++) {
            const int jc = w8 * 256 + cb * 8;   // 8 pairs = 16 candidates
            float pa[8], pb_[8];
#pragma unroll
            for (int u = 0; u < 8; u++) {
                ulonglong2 A  = A2[jc + u];
                ulonglong2 Bv = B2[jc + u];
                ull da = fma2(Bv.x, ax2, Bv.y);
                da = fma2(A.y, ax1, da);
                da = fma2(A.x, ax0, da);
                float2 va = unpack2(da);
                pa[u] = fminf(va.x, va.y);
                ull db = fma2(Bv.x, bx2, Bv.y);
                db = fma2(A.y, bx1, db);
                db = fma2(A.x, bx0, db);
                float2 vb = unpack2(db);
                pb_[u] = fminf(vb.x, vb.y);
            }
            float ca = fminf(fminf(fminf(pa[0], pa[1]), fminf(pa[2], pa[3])),
                             fminf(fminf(pa[4], pa[5]), fminf(pa[6], pa[7])));
            float cbv = fminf(fminf(fminf(pb_[0], pb_[1]), fminf(pb_[2], pb_[3])),
                              fminf(fminf(pb_[4], pb_[5]), fminf(pb_[6], pb_[7])));

            fma_ |= (ca  <= am2) ? (1u << cb) : 0u;
            fmb_ |= (cbv <= bm2) ? (1u << cb) : 0u;
            // top-3 of chunk-mins (upper bound on true 3rd distance)
            am2 = fminf(am2, fmaxf(am1, ca));
            am1 = fminf(am1, fmaxf(am0, ca));
            am0 = fminf(am0, ca);
            bm2 = fminf(bm2, fmaxf(bm1, cbv));
            bm1 = fminf(bm1, fmaxf(bm0, cbv));
            bm0 = fminf(bm0, cbv);
        }
        fa[w8] = fma_;
        fb[w8] = fmb_;
    }

    // ---- pass 2: replay flagged chunks, exact branchless merge ----
    {
        float n0 = CUDART_INF_F, n1 = CUDART_INF_F, n2 = CUDART_INF_F;
        int   i0 = 0, i1 = 0, i2 = 0;
#pragma unroll
        for (int w8 = 0; w8 < 8; w8++) {
            unsigned fm = fa[w8];
            while (fm) {
                const int cb = __ffs(fm) - 1;
                fm &= fm - 1;
                const int jc = w8 * 256 + cb * 8;
#pragma unroll
                for (int u = 0; u < 8; u++) {
                    ulonglong2 A  = A2[jc + u];
                    ulonglong2 Bv = B2[jc + u];
                    ull d = fma2(Bv.x, ax2, Bv.y);
                    d = fma2(A.y, ax1, d);
                    d = fma2(A.x, ax0, d);
                    float2 vv = unpack2(d);
                    bmerge(vv.x, 2 * (jc + u),     n0, n1, n2, i0, i1, i2);
                    bmerge(vv.y, 2 * (jc + u) + 1, n0, n1, n2, i0, i1, i2);
                }
            }
        }
        g_idx[qa * 3 + 0] = i0; g_idx[qa * 3 + 1] = i1; g_idx[qa * 3 + 2] = i2;
    }
    {
        float n0 = CUDART_INF_F, n1 = CUDART_INF_F, n2 = CUDART_INF_F;
        int   i0 = 0, i1 = 0, i2 = 0;
#pragma unroll
        for (int w8 = 0; w8 < 8; w8++) {
            unsigned fm = fb[w8];
            while (fm) {
                const int cb = __ffs(fm) - 1;
                fm &= fm - 1;
                const int jc = w8 * 256 + cb * 8;
#pragma unroll
                for (int u = 0; u < 8; u++) {
                    ulonglong2 A  = A2[jc + u];
                    ulonglong2 Bv = B2[jc + u];
                    ull d = fma2(Bv.x, bx2, Bv.y);
                    d = fma2(A.y, bx1, d);
                    d = fma2(A.x, bx0, d);
                    float2 vv = unpack2(d);
                    bmerge(vv.x, 2 * (jc + u),     n0, n1, n2, i0, i1, i2);
                    bmerge(vv.y, 2 * (jc + u) + 1, n0, n1, n2, i0, i1, i2);
                }
            }
        }
        g_idx[qb * 3 + 0] = i0; g_idx[qb * 3 + 1] = i1; g_idx[qb * 3 + 2] = i2;
    }
}

// ---------------------------------------------------------------------------
// MLP inner step: 8 points x 4 channels, h via warp-uniform broadcast LDS
// ---------------------------------------------------------------------------
__device__ __forceinline__ void gemm_step(
    const float* __restrict__ hrow,
    ulonglong2 wA, ulonglong2 wB, ulonglong2 wC, ulonglong2 wD,
    ull* a0, ull* a1, ull* a2, ull* a3) {
#pragma unroll
    for (int p = 0; p < 8; p++) {
        ulonglong2 h = *(const ulonglong2*)(hrow + p * HPAD);
        a0[p] = fma2(wA.x, h.x, a0[p]); a0[p] = fma2(wA.y, h.y, a0[p]);
        a1[p] = fma2(wB.x, h.x, a1[p]); a1[p] = fma2(wB.y, h.y, a1[p]);
        a2[p] = fma2(wC.x, h.x, a2[p]); a2[p] = fma2(wC.y, h.y, a2[p]);
        a3[p] = fma2(wD.x, h.x, a3[p]); a3[p] = fma2(wD.y, h.y, a3[p]);
    }
}

// ---------------------------------------------------------------------------
// Kernel 2: fused gather + MLP, 256 threads, 64-point tile
//   thread = (oc4 = tid&31 -> channels {oc4,+32,+64,+96}, pg = tid>>5)
//   ping-pong weight double-buffer (no register copies)
// ---------------------------------------------------------------------------
__global__ void __launch_bounds__(256, 2) mlp_kernel(
    const float* __restrict__ x, const float* __restrict__ feat,
    const float* __restrict__ b1, const float* __restrict__ b2,
    float* __restrict__ out) {
    extern __shared__ float sm[];
    float* hs = sm;               // [64][132]
    float* t1 = sm + 64 * HPAD;   // [64][132]

    const int tid = threadIdx.x;
    const int oc4 = tid & 31;
    const int pg  = tid >> 5;
    const int pb  = pg * 8;
    const int p0  = blockIdx.x * 64;
    const int b   = p0 / NN;
    const int n0  = p0 - b * NN;

    // ---- gather: 8 warps x 8 points, lane = float4 channel chunk ----
    {
        const int wid  = tid >> 5;
        const int lane = tid & 31;
        const float4* F = (const float4*)feat;
#pragma unroll
        for (int t = 0; t < 8; t++) {
            const int pt = wid * 8 + t;
            const int gq = p0 + pt;
            const int j0 = g_idx[gq * 3 + 0];
            const int j1 = g_idx[gq * 3 + 1];
            const int j2 = g_idx[gq * 3 + 2];
            float4 f0 = F[(size_t)(b * MM + j0) * 32 + lane];
            float4 f1 = F[(size_t)(b * MM + j1) * 32 + lane];
            float4 f2 = F[(size_t)(b * MM + j2) * 32 + lane];
            float4 a;
            a.x = (f0.x + f1.x + f2.x) * (1.f / 3.f);
            a.y = (f0.y + f1.y + f2.y) * (1.f / 3.f);
            a.z = (f0.z + f1.z + f2.z) * (1.f / 3.f);
            a.w = (f0.w + f1.w + f2.w) * (1.f / 3.f);
            *(float4*)&hs[pt * HPAD + lane * 4] = a;
            if (lane == 0) {
                *(float4*)&hs[pt * HPAD + 128] =
                    make_float4(x[gq * 3 + 0], x[gq * 3 + 1], x[gq * 3 + 2], 0.f);
            }
        }
    }
    __syncthreads();

    ull a0[8], a1[8], a2[8], a3[8];

    // ---- stage 1: t1 = relu(h @ w1^T + b1), 33 kq, ping-pong weights ----
    {
#pragma unroll
        for (int p = 0; p < 8; p++) { a0[p] = 0; a1[p] = 0; a2[p] = 0; a3[p] = 0; }
        const ulonglong2* w1q = (const ulonglong2*)g_w1q;
        ulonglong2 wA0 = w1q[oc4],      wB0 = w1q[oc4 + 32];
        ulonglong2 wC0 = w1q[oc4 + 64], wD0 = w1q[oc4 + 96];
        const float* hbase = hs + pb * HPAD;
#pragma unroll 1
        for (int kq = 0; kq < 32; kq += 2) {
            ulonglong2 wA1 = w1q[(kq + 1) * 128 + oc4];
            ulonglong2 wB1 = w1q[(kq + 1) * 128 + oc4 + 32];
            ulonglong2 wC1 = w1q[(kq + 1) * 128 + oc4 + 64];
            ulonglong2 wD1 = w1q[(kq + 1) * 128 + oc4 + 96];
            gemm_step(hbase + kq * 4, wA0, wB0, wC0, wD0, a0, a1, a2, a3);
            wA0 = w1q[(kq + 2) * 128 + oc4];
            wB0 = w1q[(kq + 2) * 128 + oc4 + 32];
            wC0 = w1q[(kq + 2) * 128 + oc4 + 64];
            wD0 = w1q[(kq + 2) * 128 + oc4 + 96];
            gemm_step(hbase + (kq + 1) * 4, wA1, wB1, wC1, wD1, a0, a1, a2, a3);
        }
        gemm_step(hbase + 32 * 4, wA0, wB0, wC0, wD0, a0, a1, a2, a3);  // kq=32

        const float bA = b1[oc4], bB = b1[oc4 + 32];
        const float bC = b1[oc4 + 64], bD = b1[oc4 + 96];
#pragma unroll
        for (int p = 0; p < 8; p++) {
            float2 s0 = unpack2(a0[p]), s1 = unpack2(a1[p]);
            float2 s2 = unpack2(a2[p]), s3 = unpack2(a3[p]);
            float* tr = t1 + (pb + p) * HPAD;
            tr[oc4]      = fmaxf(s0.x + s0.y + bA, 0.f);
            tr[oc4 + 32] = fmaxf(s1.x + s1.y + bB, 0.f);
            tr[oc4 + 64] = fmaxf(s2.x + s2.y + bC, 0.f);
            tr[oc4 + 96] = fmaxf(s3.x + s3.y + bD, 0.f);
        }
    }
    __syncthreads();

    // ---- stage 2: out = t1 @ w2^T + b2, 32 kq, ping-pong ----
    {
#pragma unroll
        for (int p = 0; p < 8; p++) { a0[p] = 0; a1[p] = 0; a2[p] = 0; a3[p] = 0; }
        const ulonglong2* w2q = (const ulonglong2*)g_w2q;
        ulonglong2 wA0 = w2q[oc4],      wB0 = w2q[oc4 + 32];
        ulonglong2 wC0 = w2q[oc4 + 64], wD0 = w2q[oc4 + 96];
        const float* tbase = t1 + pb * HPAD;
#pragma unroll 1
        for (int kq = 0; kq < 32; kq += 2) {
            ulonglong2 wA1 = w2q[(kq + 1) * 128 + oc4];
            ulonglong2 wB1 = w2q[(kq + 1) * 128 + oc4 + 32];
            ulonglong2 wC1 = w2q[(kq + 1) * 128 + oc4 + 64];
            ulonglong2 wD1 = w2q[(kq + 1) * 128 + oc4 + 96];
            gemm_step(tbase + kq * 4, wA0, wB0, wC0, wD0, a0, a1, a2, a3);
            wA0 = w2q[(kq + 2) * 128 + oc4];
            wB0 = w2q[(kq + 2) * 128 + oc4 + 32];
            wC0 = w2q[(kq + 2) * 128 + oc4 + 64];
            wD0 = w2q[(kq + 2) * 128 + oc4 + 96];
            gemm_step(tbase + (kq + 1) * 4, wA1, wB1, wC1, wD1, a0, a1, a2, a3);
        }
        const float bA = b2[oc4], bB = b2[oc4 + 32];
        const float bC = b2[oc4 + 64], bD = b2[oc4 + 96];
        float* s_o = hs;   // reuse, stride 129 (conflict-free transpose)
#pragma unroll
        for (int p = 0; p < 8; p++) {
            float2 s0 = unpack2(a0[p]), s1 = unpack2(a1[p]);
            float2 s2 = unpack2(a2[p]), s3 = unpack2(a3[p]);
            float* sr = s_o + (pb + p) * 129;
            sr[oc4]      = s0.x + s0.y + bA;
            sr[oc4 + 32] = s1.x + s1.y + bB;
            sr[oc4 + 64] = s2.x + s2.y + bC;
            sr[oc4 + 96] = s3.x + s3.y + bD;
        }
    }
    __syncthreads();

    // ---- coalesced transposed store: out[b][oc][n0+p] ----
    {
        const float* s_o = hs;
        float* ob = out + (size_t)b * OUTC * NN + n0;
        for (int idx = tid; idx < 128 * 64; idx += 256) {
            const int oc = idx >> 6;
            const int p  = idx & 63;
            ob[(size_t)oc * NN + p] = s_o[p * 129 + oc];
        }
    }
}

// ---------------------------------------------------------------------------
extern "C" void kernel_launch(void* const* d_in, const int* in_sizes, int n_in,
                              void* d_out, int out_size) {
    const float* x   = (const float*)d_in[0];
    const float* sx  = (const float*)d_in[1];
    const float* ft  = (const float*)d_in[2];
    const float* w1  = (const float*)d_in[3];
    const float* b1  = (const float*)d_in[4];
    const float* w2  = (const float*)d_in[5];
    const float* b2  = (const float*)d_in[6];
    float* out = (float*)d_out;

    const int knn_smem = MM * sizeof(float4);            // 64 KB
    const int mlp_smem = 2 * 64 * HPAD * sizeof(float);  // 67.6 KB

    cudaFuncSetAttribute(knn_kernel,
                         cudaFuncAttributeMaxDynamicSharedMemorySize, knn_smem);
    cudaFuncSetAttribute(mlp_kernel,
                         cudaFuncAttributeMaxDynamicSharedMemorySize, mlp_smem);

    // 256 knn blocks total (256 queries each), split so ncu captures knn
    wprep_kernel<<<WPREP_BLOCKS, 128>>>(w1, w2);
    knn_kernel<<<128, 128, knn_smem>>>(x, sx, 0);
    knn_kernel<<<128, 128, knn_smem>>>(x, sx, 128);
    mlp_kernel<<<(BB * NN) / 64, 256, mlp_smem>>>(x, ft, b1, b2, out);
}